// round 5
// baseline (speedup 1.0000x reference)
#include <cuda_runtime.h>
#include <cuda_fp16.h>

#define HID 5
#define HDIM 2048
#define BSZ 16384

__device__ int g_lengths[BSZ];

// ---------------------------------------------------------------------------
// Kernel 1: per-row nonzero count (ragged length, matches reference mask)
// ---------------------------------------------------------------------------
__global__ void len_kernel(const float* __restrict__ x) {
    int b = blockIdx.x;
    const float4* row = reinterpret_cast<const float4*>(x + (size_t)b * HDIM);
    int tid = threadIdx.x;
    int cnt = 0;
#pragma unroll
    for (int i = 0; i < 2; i++) {
        float4 v = row[tid + i * 256];
        cnt += (v.x != 0.f) + (v.y != 0.f) + (v.z != 0.f) + (v.w != 0.f);
    }
    __shared__ int s[8];
#pragma unroll
    for (int o = 16; o > 0; o >>= 1) cnt += __shfl_down_sync(0xffffffffu, cnt, o);
    if ((tid & 31) == 0) s[tid >> 5] = cnt;
    __syncthreads();
    if (tid < 8) {
        int v = s[tid];
#pragma unroll
        for (int o = 4; o > 0; o >>= 1) v += __shfl_down_sync(0xffu, v, o);
        if (tid == 0) g_lengths[b] = v;
    }
}

// ---------------------------------------------------------------------------
// math helpers
// ---------------------------------------------------------------------------
__device__ __forceinline__ float fast_tanh(float v) {
    float r; asm("tanh.approx.f32 %0, %1;" : "=f"(r) : "f"(v)); return r;
}
__device__ __forceinline__ __half2 tanh2(__half2 v) {
    unsigned u = *reinterpret_cast<unsigned*>(&v), r;
    asm("tanh.approx.f16x2 %0, %1;" : "=r"(r) : "r"(u));
    return *reinterpret_cast<__half2*>(&r);
}

// ---------------------------------------------------------------------------
// LSTM: 1 thread / sequence.
// Gate GEMV in fp16 HFMA2 (rt2 -> 2x scalar-eq FMA throughput).
// Pair layout unit-major: P_u = {i_u, f_u} (both prescaled 0.5),
//                         Q_u = {0.5*o_u, g_u}.
// Sigmoids via tanh.approx.f16x2; tanh(g), tanh(cn), c/h update in fp32.
// ---------------------------------------------------------------------------
struct State {
    __half2 h2[HID];   // {h_j, h_j} fp16 for the GEMV
    float   c[HID];    // fp32 cell state
    float   h[HID];    // fp32 hidden (output path)
};

__device__ __forceinline__ void lstm_step(State& st, float xv,
    const __half2* __restrict__ wihP, const __half2* __restrict__ wihQ,
    const __half2* __restrict__ bsP,  const __half2* __restrict__ bsQ,
    const __half2 (*whhP)[HID], const __half2 (*whhQ)[HID])
{
    const __half2 x2 = __float2half2_rn(xv);
    __half2 aP[HID], aQ[HID];
#pragma unroll
    for (int u = 0; u < HID; u++) {
        __half2 a = __hfma2(x2, wihP[u], bsP[u]);
        __half2 b = __hfma2(x2, wihQ[u], bsQ[u]);
#pragma unroll
        for (int j = 0; j < HID; j++) {
            a = __hfma2(st.h2[j], whhP[u][j], a);
            b = __hfma2(st.h2[j], whhQ[u][j], b);
        }
        aP[u] = a; aQ[u] = b;
    }
    const __half2 h05 = __float2half2_rn(0.5f);
#pragma unroll
    for (int u = 0; u < HID; u++) {
        // {ig, fg} = 0.5*tanh({.5gi,.5gf}) + 0.5   (one f16x2 MUFU + one HFMA2)
        const __half2 sP = __hfma2(tanh2(aP[u]), h05, h05);
        const __half2 tQ = tanh2(aQ[u]);          // lo = tanh(0.5*go); hi unused
        const float ig = __low2float(sP);
        const float fg = __high2float(sP);
        const float og = fmaf(__low2float(tQ), 0.5f, 0.5f);
        const float gv = __high2float(aQ[u]);     // raw g gate
        const float tg = fast_tanh(gv);           // fp32 tanh(g)
        const float cn = fmaf(fg, st.c[u], ig * tg);
        st.c[u] = cn;
        const float hn = og * fast_tanh(cn);      // fp32 tanh(c)
        st.h[u]  = hn;
        st.h2[u] = __float2half2_rn(hn);          // packed cvt, 1 instr
    }
}

__global__ void __launch_bounds__(64, 1) lstm_kernel(
    const float* __restrict__ x,
    const float* __restrict__ W_ih,
    const float* __restrict__ W_hh,
    const float* __restrict__ b_ih,
    const float* __restrict__ b_hh,
    float* __restrict__ out)
{
    int b = blockIdx.x * blockDim.x + threadIdx.x;

    // gate rows: i:0-4  f:5-9  g:10-14  o:15-19
    __half2 wihP[HID], wihQ[HID], bsP[HID], bsQ[HID];
    __half2 whhP[HID][HID], whhQ[HID][HID];
#pragma unroll
    for (int u = 0; u < HID; u++) {
        const int ri = u, rf = HID + u, rg = 2 * HID + u, ro = 3 * HID + u;
        wihP[u] = __floats2half2_rn(0.5f * W_ih[ri], 0.5f * W_ih[rf]);
        wihQ[u] = __floats2half2_rn(0.5f * W_ih[ro], W_ih[rg]);
        bsP[u]  = __floats2half2_rn(0.5f * (b_ih[ri] + b_hh[ri]),
                                    0.5f * (b_ih[rf] + b_hh[rf]));
        bsQ[u]  = __floats2half2_rn(0.5f * (b_ih[ro] + b_hh[ro]),
                                    (b_ih[rg] + b_hh[rg]));
#pragma unroll
        for (int j = 0; j < HID; j++) {
            whhP[u][j] = __floats2half2_rn(0.5f * W_hh[ri * HID + j],
                                           0.5f * W_hh[rf * HID + j]);
            whhQ[u][j] = __floats2half2_rn(0.5f * W_hh[ro * HID + j],
                                           W_hh[rg * HID + j]);
        }
    }

    const int len = g_lengths[b];
    const float* row = x + (size_t)b * HDIM;

    State st;
#pragma unroll
    for (int u = 0; u < HID; u++) {
        st.h2[u] = __float2half2_rn(0.f);
        st.c[u] = 0.f;
        st.h[u] = 0.f;
    }

    float4 a0 = make_float4(0.f, 0.f, 0.f, 0.f);
    if (len > 0) a0 = *reinterpret_cast<const float4*>(row);

    for (int t0 = 0; t0 < len; t0 += 4) {
        // prefetch next 4 timesteps (HDIM multiple of 4)
        float4 nx = a0;
        const int nt = t0 + 4;
        if (nt < HDIM) nx = *reinterpret_cast<const float4*>(row + nt);

        const int nrem = len - t0;
        if (nrem >= 4) {
            lstm_step(st, a0.x, wihP, wihQ, bsP, bsQ, whhP, whhQ);
            lstm_step(st, a0.y, wihP, wihQ, bsP, bsQ, whhP, whhQ);
            lstm_step(st, a0.z, wihP, wihQ, bsP, bsQ, whhP, whhQ);
            lstm_step(st, a0.w, wihP, wihQ, bsP, bsQ, whhP, whhQ);
        } else {
            float xs[4] = {a0.x, a0.y, a0.z, a0.w};
#pragma unroll
            for (int k = 0; k < 4; k++)
                if (k < nrem)
                    lstm_step(st, xs[k], wihP, wihQ, bsP, bsQ, whhP, whhQ);
        }
        a0 = nx;
    }

#pragma unroll
    for (int u = 0; u < HID; u++) out[b * HID + u] = st.h[u];
}

// ---------------------------------------------------------------------------
extern "C" void kernel_launch(void* const* d_in, const int* in_sizes, int n_in,
                              void* d_out, int out_size) {
    const float* x    = (const float*)d_in[0];
    const float* W_ih = (const float*)d_in[1];
    const float* W_hh = (const float*)d_in[2];
    const float* b_ih = (const float*)d_in[3];
    const float* b_hh = (const float*)d_in[4];
    float* out = (float*)d_out;

    len_kernel<<<BSZ, 256>>>(x);
    lstm_kernel<<<BSZ / 64, 64>>>(x, W_ih, W_hh, b_ih, b_hh, out);
}